// round 2
// baseline (speedup 1.0000x reference)
#include <cuda_runtime.h>
#include <math.h>

#define BATCH 32
#define H 512
#define W 512
#define HW (H*W)
#define NTOT (BATCH*HW)
#define KRAD 15
#define KK_INV (1.0f/961.0f)

// Pass-2 tiling: 2 column strips x 8 row chunks x 32 images = 512 blocks, 256 thr
#define COLS_PB 256
#define ROWS_PB 64
#define NBLK2 512

// Scratch (allocation-free: __device__ globals)
__device__ float g_hsum[NTOT];          // horizontal 31-wide box sums of y_target
__device__ float g_part[NBLK2][4];      // per-block partials {bce, wsum, inter, union}

// ---------------------------------------------------------------------------
// Pass 1: per-row inclusive prefix scan -> horizontal box sum (zero padded)
// One block per row (512 threads).
// ---------------------------------------------------------------------------
__global__ void hpass_kernel(const float* __restrict__ targ) {
    const int row = blockIdx.x;          // 0 .. BATCH*H-1
    const int x   = threadIdx.x;         // 0 .. 511
    __shared__ float buf[2][W];

    buf[0][x] = targ[(size_t)row * W + x];
    __syncthreads();

    int s = 0;
    #pragma unroll
    for (int off = 1; off < W; off <<= 1) {
        float v = buf[s][x];
        if (x >= off) v += buf[s][x - off];
        buf[s ^ 1][x] = v;
        __syncthreads();
        s ^= 1;
    }
    // box sum over [x-15, x+15] with zero pad
    const int hi = (x + KRAD < W - 1) ? (x + KRAD) : (W - 1);
    float sum = buf[s][hi];
    if (x >= KRAD + 1) sum -= buf[s][x - KRAD - 1];
    g_hsum[(size_t)row * W + x] = sum;
}

// ---------------------------------------------------------------------------
// Pass 2: vertical sliding-window box sum fused with the full loss math.
// grid = (2, 8, 32), block = 256. Each thread owns one column for 64 out rows.
// ---------------------------------------------------------------------------
__global__ void loss_kernel(const float* __restrict__ pred,
                            const float* __restrict__ targ) {
    const int b   = blockIdx.z;
    const int x   = blockIdx.x * COLS_PB + threadIdx.x;
    const int r0  = blockIdx.y * ROWS_PB;
    const int tid = threadIdx.x;

    const float* __restrict__ hs = g_hsum + (size_t)b * HW;
    const float* __restrict__ pb = pred   + (size_t)b * HW;
    const float* __restrict__ tb = targ   + (size_t)b * HW;

    // Build initial vertical window for output row r0: rows [r0-15, r0+15]
    float vs = 0.0f;
    #pragma unroll
    for (int dr = -KRAD; dr <= KRAD; ++dr) {
        const int rr = r0 + dr;
        if (rr >= 0 && rr < H) vs += hs[rr * W + x];
    }

    float bce_a = 0.0f, wsum_a = 0.0f, inter_a = 0.0f, uni_a = 0.0f;

    for (int r = r0; r < r0 + ROWS_PB; ++r) {
        const float tv = tb[r * W + x];
        const float xv = pb[r * W + x];

        // adaptive weight
        const float pool = vs * KK_INV;
        const float w = fmaf(5.0f, fabsf(pool - tv), 1.0f);

        // stable softplus + sigmoid sharing one exp
        const float E  = expf(-fabsf(xv));
        const float sp = fmaxf(xv, 0.0f) + log1pf(E);
        const float inv1pE = 1.0f / (1.0f + E);
        const float p  = (xv >= 0.0f) ? inv1pE : E * inv1pE;

        bce_a   += sp - xv * tv;
        wsum_a  += w;
        inter_a += p * tv * w;
        uni_a   += (p + tv) * w;

        // slide window down one row
        const int radd = r + KRAD + 1;
        const int rsub = r - KRAD;
        if (radd < H)  vs += hs[radd * W + x];
        if (rsub >= 0) vs -= hs[rsub * W + x];
    }

    // Deterministic block reduction (fixed order), write to fixed slot.
    __shared__ float red[4][COLS_PB];
    red[0][tid] = bce_a;
    red[1][tid] = wsum_a;
    red[2][tid] = inter_a;
    red[3][tid] = uni_a;
    __syncthreads();
    #pragma unroll
    for (int off = COLS_PB / 2; off > 0; off >>= 1) {
        if (tid < off) {
            red[0][tid] += red[0][tid + off];
            red[1][tid] += red[1][tid + off];
            red[2][tid] += red[2][tid + off];
            red[3][tid] += red[3][tid + off];
        }
        __syncthreads();
    }
    if (tid == 0) {
        const int blin = (blockIdx.z * gridDim.y + blockIdx.y) * gridDim.x + blockIdx.x;
        g_part[blin][0] = red[0][0];
        g_part[blin][1] = red[1][0];
        g_part[blin][2] = red[2][0];
        g_part[blin][3] = red[3][0];
    }
}

// ---------------------------------------------------------------------------
// Pass 3: finalize. One block, 256 threads, fixed-order sums.
// ---------------------------------------------------------------------------
__global__ void finalize_kernel(float* __restrict__ out) {
    const int tid = threadIdx.x;
    __shared__ float sb[256];
    __shared__ float res[BATCH];

    // global BCE sum over all 512 block partials
    sb[tid] = g_part[tid][0] + g_part[tid + 256][0];
    __syncthreads();
    #pragma unroll
    for (int off = 128; off > 0; off >>= 1) {
        if (tid < off) sb[tid] += sb[tid + off];
        __syncthreads();
    }
    const float bce = sb[0] * (1.0f / (float)NTOT);

    // per-image terms: each image owns 16 consecutive partial slots
    if (tid < BATCH) {
        float ws = 0.0f, it = 0.0f, un = 0.0f;
        #pragma unroll
        for (int j = 0; j < 16; ++j) {
            const int bl = tid * 16 + j;
            ws += g_part[bl][1];
            it += g_part[bl][2];
            un += g_part[bl][3];
        }
        const float w_bce = (ws * bce + 1e-8f) / (ws + 1e-8f);
        const float w_iou = 1.0f - (it + 1.0f + 1e-8f) / (un - it + 1.0f + 1e-8f);
        res[tid] = w_bce + w_iou;
    }
    __syncthreads();
    if (tid == 0) {
        float acc = 0.0f;
        #pragma unroll
        for (int i = 0; i < BATCH; ++i) acc += res[i];
        out[0] = acc * (1.0f / (float)BATCH);
    }
}

// ---------------------------------------------------------------------------
extern "C" void kernel_launch(void* const* d_in, const int* in_sizes, int n_in,
                              void* d_out, int out_size) {
    const float* y_pred   = (const float*)d_in[0];
    const float* y_target = (const float*)d_in[1];
    float* out = (float*)d_out;

    hpass_kernel<<<BATCH * H, W>>>(y_target);

    dim3 g2(W / COLS_PB, H / ROWS_PB, BATCH);   // (2, 8, 32)
    loss_kernel<<<g2, COLS_PB>>>(y_pred, y_target);

    finalize_kernel<<<1, 256>>>(out);
}

// round 3
// speedup vs baseline: 1.3426x; 1.3426x over previous
#include <cuda_runtime.h>
#include <math.h>

#define BATCH 32
#define H 512
#define W 512
#define HW (H*W)
#define NTOT (BATCH*HW)
#define KRAD 15
#define KK_INV (1.0f/961.0f)

// Pass-2 tiling: 2 col strips (128 thr x float2 = 256 cols) x 8 row chunks x 32 imgs
#define T2 128
#define ROWS_PB 64
#define NBLK2 512

__device__ float g_hsum[NTOT];       // horizontal 31-wide box sums of y_target
__device__ float g_part[NBLK2][4];   // per-block partials {bce, wsum, inter, union}

// ---------------------------------------------------------------------------
// Pass 1: warp-per-row horizontal box sum via register prefix + shfl gather.
// No shared memory, no barriers. 16 chunks of 32 per row.
// ---------------------------------------------------------------------------
__global__ void hpass_kernel(const float* __restrict__ targ) {
    const unsigned FULL = 0xffffffffu;
    const int warp_id = blockIdx.x * (blockDim.x >> 5) + (threadIdx.x >> 5);
    const int lane = threadIdx.x & 31;
    const float* __restrict__ rowp = targ   + (size_t)warp_id * W;
    float*       __restrict__ outp = g_hsum + (size_t)warp_id * W;

    float carry = 0.0f;     // sum of all previous chunks
    float Pprev = 0.0f;     // global inclusive prefix, chunk c-2
    float Pcur  = 0.0f;     // global inclusive prefix, chunk c-1

    #pragma unroll
    for (int c = 0; c < 16; ++c) {
        float v = rowp[c * 32 + lane];
        // inclusive warp prefix sum
        #pragma unroll
        for (int off = 1; off < 32; off <<= 1) {
            float n = __shfl_up_sync(FULL, v, off);
            if (lane >= off) v += n;
        }
        float Pnext = carry + v;                    // global prefix of chunk c
        carry += __shfl_sync(FULL, v, 31);

        if (c > 0) {
            // emit chunk m = c-1:  out[x] = P[min(x+15,511)] - (x>=16 ? P[x-16] : 0)
            float a1 = __shfl_sync(FULL, Pcur,  (lane + 15) & 31);
            float a2 = __shfl_sync(FULL, Pnext, (lane - 17) & 31);
            float A  = (lane <= 16) ? a1 : a2;
            float b1 = __shfl_sync(FULL, Pcur,  (lane - 16) & 31);
            float b2 = __shfl_sync(FULL, Pprev, (lane + 16) & 31);
            float B  = (lane >= 16) ? b1 : b2;
            outp[(c - 1) * 32 + lane] = A - B;
        }
        Pprev = Pcur;
        Pcur  = Pnext;
    }
    // emit last chunk (m = 15); indices beyond 511 clamp to total = carry
    {
        float total = carry;
        float a1 = __shfl_sync(FULL, Pcur, (lane + 15) & 31);
        float A  = (lane <= 16) ? a1 : total;
        float b1 = __shfl_sync(FULL, Pcur,  (lane - 16) & 31);
        float b2 = __shfl_sync(FULL, Pprev, (lane + 16) & 31);
        float B  = (lane >= 16) ? b1 : b2;
        outp[15 * 32 + lane] = A - B;
    }
}

// ---------------------------------------------------------------------------
// Pass 2: vertical sliding-window box sum fused with loss math, float2 wide.
// grid = (2, 8, 32), block = 128. Each thread owns 2 adjacent columns.
// ---------------------------------------------------------------------------
__global__ void loss_kernel(const float* __restrict__ pred,
                            const float* __restrict__ targ) {
    const int b   = blockIdx.z;
    const int tid = threadIdx.x;
    const int x2  = blockIdx.x * T2 + tid;       // float2 column index (0..255)
    const int r0  = blockIdx.y * ROWS_PB;

    const float2* __restrict__ hs = (const float2*)(g_hsum + (size_t)b * HW);
    const float2* __restrict__ pb = (const float2*)(pred   + (size_t)b * HW);
    const float2* __restrict__ tb = (const float2*)(targ   + (size_t)b * HW);
    const int W2 = W / 2;

    // initial vertical window: rows [r0-15, r0+15]
    float2 vs = make_float2(0.0f, 0.0f);
    #pragma unroll
    for (int dr = -KRAD; dr <= KRAD; ++dr) {
        const int rr = r0 + dr;
        if (rr >= 0 && rr < H) {
            float2 h = hs[rr * W2 + x2];
            vs.x += h.x; vs.y += h.y;
        }
    }

    float bce_a = 0.0f, wsum_a = 0.0f, inter_a = 0.0f, uni_a = 0.0f;

    for (int r = r0; r < r0 + ROWS_PB; ++r) {
        const float2 tv = tb[r * W2 + x2];
        const float2 xv = pb[r * W2 + x2];

        // lane .x
        {
            const float w = fmaf(5.0f, fabsf(vs.x * KK_INV - tv.x), 1.0f);
            const float E = __expf(-fabsf(xv.x));
            const float u = 1.0f + E;
            const float sp = fmaxf(xv.x, 0.0f) + __logf(u);
            const float inv = __fdividef(1.0f, u);
            const float p = (xv.x >= 0.0f) ? inv : E * inv;
            bce_a   += sp - xv.x * tv.x;
            wsum_a  += w;
            inter_a += p * tv.x * w;
            uni_a   += (p + tv.x) * w;
        }
        // lane .y
        {
            const float w = fmaf(5.0f, fabsf(vs.y * KK_INV - tv.y), 1.0f);
            const float E = __expf(-fabsf(xv.y));
            const float u = 1.0f + E;
            const float sp = fmaxf(xv.y, 0.0f) + __logf(u);
            const float inv = __fdividef(1.0f, u);
            const float p = (xv.y >= 0.0f) ? inv : E * inv;
            bce_a   += sp - xv.y * tv.y;
            wsum_a  += w;
            inter_a += p * tv.y * w;
            uni_a   += (p + tv.y) * w;
        }

        // slide window down one row
        const int radd = r + KRAD + 1;
        const int rsub = r - KRAD;
        if (radd < H) {
            float2 h = hs[radd * W2 + x2];
            vs.x += h.x; vs.y += h.y;
        }
        if (rsub >= 0) {
            float2 h = hs[rsub * W2 + x2];
            vs.x -= h.x; vs.y -= h.y;
        }
    }

    // deterministic block reduction (fixed order)
    __shared__ float red[4][T2];
    red[0][tid] = bce_a;
    red[1][tid] = wsum_a;
    red[2][tid] = inter_a;
    red[3][tid] = uni_a;
    __syncthreads();
    #pragma unroll
    for (int off = T2 / 2; off > 0; off >>= 1) {
        if (tid < off) {
            red[0][tid] += red[0][tid + off];
            red[1][tid] += red[1][tid + off];
            red[2][tid] += red[2][tid + off];
            red[3][tid] += red[3][tid + off];
        }
        __syncthreads();
    }
    if (tid == 0) {
        const int blin = (blockIdx.z * gridDim.y + blockIdx.y) * gridDim.x + blockIdx.x;
        g_part[blin][0] = red[0][0];
        g_part[blin][1] = red[1][0];
        g_part[blin][2] = red[2][0];
        g_part[blin][3] = red[3][0];
    }
}

// ---------------------------------------------------------------------------
// Pass 3: finalize. One block, 256 threads, fixed-order sums.
// ---------------------------------------------------------------------------
__global__ void finalize_kernel(float* __restrict__ out) {
    const int tid = threadIdx.x;
    __shared__ float sb[256];
    __shared__ float res[BATCH];

    sb[tid] = g_part[tid][0] + g_part[tid + 256][0];
    __syncthreads();
    #pragma unroll
    for (int off = 128; off > 0; off >>= 1) {
        if (tid < off) sb[tid] += sb[tid + off];
        __syncthreads();
    }
    const float bce = sb[0] * (1.0f / (float)NTOT);

    if (tid < BATCH) {
        float ws = 0.0f, it = 0.0f, un = 0.0f;
        #pragma unroll
        for (int j = 0; j < 16; ++j) {
            const int bl = tid * 16 + j;
            ws += g_part[bl][1];
            it += g_part[bl][2];
            un += g_part[bl][3];
        }
        const float w_bce = (ws * bce + 1e-8f) / (ws + 1e-8f);
        const float w_iou = 1.0f - (it + 1.0f + 1e-8f) / (un - it + 1.0f + 1e-8f);
        res[tid] = w_bce + w_iou;
    }
    __syncthreads();
    if (tid == 0) {
        float acc = 0.0f;
        #pragma unroll
        for (int i = 0; i < BATCH; ++i) acc += res[i];
        out[0] = acc * (1.0f / (float)BATCH);
    }
}

// ---------------------------------------------------------------------------
extern "C" void kernel_launch(void* const* d_in, const int* in_sizes, int n_in,
                              void* d_out, int out_size) {
    const float* y_pred   = (const float*)d_in[0];
    const float* y_target = (const float*)d_in[1];
    float* out = (float*)d_out;

    // 16384 rows, one warp each; 8 warps per block
    hpass_kernel<<<BATCH * H / 8, 256>>>(y_target);

    dim3 g2(2, H / ROWS_PB, BATCH);   // (2, 8, 32)
    loss_kernel<<<g2, T2>>>(y_pred, y_target);

    finalize_kernel<<<1, 256>>>(out);
}

// round 4
// speedup vs baseline: 3.3081x; 2.4639x over previous
#include <cuda_runtime.h>
#include <math.h>

#define BATCH 32
#define H 512
#define W 512
#define HW (H*W)
#define NTOT (BATCH*HW)
#define KRAD 15
#define KK_INV (1.0f/961.0f)

#define ROWS_PB 16
#define NBLK2 (BATCH * (H / ROWS_PB))   // 1024

__device__ __align__(16) float g_hsum[NTOT];   // horizontal 31-wide box sums
__device__ float g_part[NBLK2][4];             // {bce, wsum, inter, union}

// ---------------------------------------------------------------------------
// Pass 1: warp-per-row horizontal box sum.
// Register-quad prefix + 5-shuffle warp scan -> full-row prefix P in smem ->
// out[x] = P[min(x+15,511)] - (x>=16 ? P[x-16] : 0) via aligned LDS.128.
// All communication intra-warp (syncwarp only).
// ---------------------------------------------------------------------------
__global__ void hpass_kernel(const float* __restrict__ targ) {
    const unsigned FULL = 0xffffffffu;
    const int wslot = threadIdx.x >> 5;
    const int lane  = threadIdx.x & 31;
    const int row   = blockIdx.x * (blockDim.x >> 5) + wslot;

    __shared__ float Psm[8][W];          // 8 warps * 2KB
    float* Pw = Psm[wslot];
    float4* P4 = (float4*)Pw;

    const float4* __restrict__ rowp = (const float4*)(targ + (size_t)row * W);
    float4*       __restrict__ outp = (float4*)(g_hsum + (size_t)row * W);

    float carry = 0.0f;
    #pragma unroll
    for (int c = 0; c < 4; ++c) {
        float4 q = rowp[c * 32 + lane];
        float p0 = q.x;
        float p1 = p0 + q.y;
        float p2 = p1 + q.z;
        float p3 = p2 + q.w;
        // warp inclusive scan of quad totals
        float s = p3;
        #pragma unroll
        for (int off = 1; off < 32; off <<= 1) {
            float n = __shfl_up_sync(FULL, s, off);
            if (lane >= off) s += n;
        }
        const float base = s - p3 + carry;
        P4[c * 32 + lane] = make_float4(base + p0, base + p1, base + p2, base + p3);
        carry += __shfl_sync(FULL, s, 31);
    }
    __syncwarp();

    const float total = Pw[W - 1];
    #pragma unroll
    for (int c = 0; c < 4; ++c) {
        const int g = c * 32 + lane;         // output quad index 0..127
        float4 A;
        if (g < 124) {
            float4 Q1 = P4[g + 3];
            float4 Q2 = P4[g + 4];
            A = make_float4(Q1.w, Q2.x, Q2.y, Q2.z);
        } else {
            // x = 4g+j >= 496  ->  min(x+15,511) == 511 for all j
            A = make_float4(total, total, total, total);
        }
        float4 B;
        if (g >= 4) B = P4[g - 4];           // P[x-16], aligned
        else        B = make_float4(0.f, 0.f, 0.f, 0.f);  // x<16 -> 0
        outp[g] = make_float4(A.x - B.x, A.y - B.y, A.z - B.z, A.w - B.w);
    }
}

// ---------------------------------------------------------------------------
// Pass 2: vertical sliding-window box sum fused with loss math, float4 wide.
// grid = (H/16, BATCH), block = 128. Thread t owns col quad [4t,4t+3],
// 16 output rows.
// ---------------------------------------------------------------------------
__device__ __forceinline__ void lane_math(float xv, float tv, float vsum,
                                          float& bce, float& ws, float& it, float& un) {
    const float w   = fmaf(5.0f, fabsf(vsum * KK_INV - tv), 1.0f);
    const float E   = __expf(-fabsf(xv));
    const float u   = 1.0f + E;
    const float sp  = fmaxf(xv, 0.0f) + __logf(u);
    const float inv = __fdividef(1.0f, u);
    const float p   = (xv >= 0.0f) ? inv : E * inv;
    bce += sp - xv * tv;
    ws  += w;
    it  += p * tv * w;
    un  += (p + tv) * w;
}

__global__ void loss_kernel(const float* __restrict__ pred,
                            const float* __restrict__ targ) {
    const int b   = blockIdx.y;
    const int tid = threadIdx.x;          // 0..127 -> col quad
    const int r0  = blockIdx.x * ROWS_PB;
    const int W4  = W / 4;

    const float4* __restrict__ hs = (const float4*)(g_hsum + (size_t)b * HW);
    const float4* __restrict__ pb = (const float4*)(pred   + (size_t)b * HW);
    const float4* __restrict__ tb = (const float4*)(targ   + (size_t)b * HW);

    // initial vertical window: rows [r0-15, r0+15]
    float4 vs = make_float4(0.f, 0.f, 0.f, 0.f);
    #pragma unroll
    for (int dr = -KRAD; dr <= KRAD; ++dr) {
        const int rr = r0 + dr;
        if (rr >= 0 && rr < H) {
            float4 h = hs[rr * W4 + tid];
            vs.x += h.x; vs.y += h.y; vs.z += h.z; vs.w += h.w;
        }
    }

    float bce_a = 0.f, wsum_a = 0.f, inter_a = 0.f, uni_a = 0.f;

    #pragma unroll 4
    for (int r = r0; r < r0 + ROWS_PB; ++r) {
        const float4 tv = tb[r * W4 + tid];
        const float4 xv = pb[r * W4 + tid];
        const int radd = r + KRAD + 1;
        const int rsub = r - KRAD;
        float4 ha = (radd < H)  ? hs[radd * W4 + tid] : make_float4(0.f,0.f,0.f,0.f);
        float4 hsub = (rsub >= 0) ? hs[rsub * W4 + tid] : make_float4(0.f,0.f,0.f,0.f);

        lane_math(xv.x, tv.x, vs.x, bce_a, wsum_a, inter_a, uni_a);
        lane_math(xv.y, tv.y, vs.y, bce_a, wsum_a, inter_a, uni_a);
        lane_math(xv.z, tv.z, vs.z, bce_a, wsum_a, inter_a, uni_a);
        lane_math(xv.w, tv.w, vs.w, bce_a, wsum_a, inter_a, uni_a);

        vs.x += ha.x - hsub.x;
        vs.y += ha.y - hsub.y;
        vs.z += ha.z - hsub.z;
        vs.w += ha.w - hsub.w;
    }

    // deterministic block reduction (fixed order)
    __shared__ float red[4][128];
    red[0][tid] = bce_a;
    red[1][tid] = wsum_a;
    red[2][tid] = inter_a;
    red[3][tid] = uni_a;
    __syncthreads();
    #pragma unroll
    for (int off = 64; off > 0; off >>= 1) {
        if (tid < off) {
            red[0][tid] += red[0][tid + off];
            red[1][tid] += red[1][tid + off];
            red[2][tid] += red[2][tid + off];
            red[3][tid] += red[3][tid + off];
        }
        __syncthreads();
    }
    if (tid == 0) {
        const int blin = b * gridDim.x + blockIdx.x;   // image-major
        g_part[blin][0] = red[0][0];
        g_part[blin][1] = red[1][0];
        g_part[blin][2] = red[2][0];
        g_part[blin][3] = red[3][0];
    }
}

// ---------------------------------------------------------------------------
// Pass 3: finalize. One block, 256 threads, fixed-order sums.
// ---------------------------------------------------------------------------
#define CHUNKS_PER_IMG (H / ROWS_PB)   // 32
__global__ void finalize_kernel(float* __restrict__ out) {
    const int tid = threadIdx.x;
    __shared__ float sb[256];
    __shared__ float res[BATCH];

    // global BCE sum over all 1024 block partials (4 per thread, fixed order)
    float acc = 0.0f;
    #pragma unroll
    for (int j = 0; j < NBLK2 / 256; ++j) acc += g_part[tid * (NBLK2 / 256) + j][0];
    sb[tid] = acc;
    __syncthreads();
    #pragma unroll
    for (int off = 128; off > 0; off >>= 1) {
        if (tid < off) sb[tid] += sb[tid + off];
        __syncthreads();
    }
    const float bce = sb[0] * (1.0f / (float)NTOT);

    if (tid < BATCH) {
        float ws = 0.0f, it = 0.0f, un = 0.0f;
        #pragma unroll
        for (int j = 0; j < CHUNKS_PER_IMG; ++j) {
            const int bl = tid * CHUNKS_PER_IMG + j;
            ws += g_part[bl][1];
            it += g_part[bl][2];
            un += g_part[bl][3];
        }
        const float w_bce = (ws * bce + 1e-8f) / (ws + 1e-8f);
        const float w_iou = 1.0f - (it + 1.0f + 1e-8f) / (un - it + 1.0f + 1e-8f);
        res[tid] = w_bce + w_iou;
    }
    __syncthreads();
    if (tid == 0) {
        float a = 0.0f;
        #pragma unroll
        for (int i = 0; i < BATCH; ++i) a += res[i];
        out[0] = a * (1.0f / (float)BATCH);
    }
}

// ---------------------------------------------------------------------------
extern "C" void kernel_launch(void* const* d_in, const int* in_sizes, int n_in,
                              void* d_out, int out_size) {
    const float* y_pred   = (const float*)d_in[0];
    const float* y_target = (const float*)d_in[1];
    float* out = (float*)d_out;

    hpass_kernel<<<BATCH * H / 8, 256>>>(y_target);            // 2048 blocks, 8 warps
    dim3 g2(H / ROWS_PB, BATCH);                               // (32, 32)
    loss_kernel<<<g2, 128>>>(y_pred, y_target);
    finalize_kernel<<<1, 256>>>(out);
}

// round 6
// speedup vs baseline: 3.5756x; 1.0808x over previous
#include <cuda_runtime.h>
#include <cuda_fp16.h>
#include <math.h>

#define BATCH 32
#define H 512
#define W 512
#define HW (H*W)
#define NTOT (BATCH*HW)
#define KRAD 15
#define KK_INV (1.0f/961.0f)

#define ROWS_PB 32
#define NSLOT 36
#define NBLK (BATCH * (H / ROWS_PB))      // 512
#define CHUNKS_PER_IMG (H / ROWS_PB)      // 16

__device__ float g_part[NBLK][4];         // {bce, wsum, inter, union}

__device__ __forceinline__ int slotof(int row) {
    return (unsigned)(row + 72) % NSLOT;
}

// Warp computes the 31-wide horizontal box sum of one targ row and stores it
// (as fp16) into a circular-buffer row. Rows outside [0,H) are stored as zero.
__device__ __forceinline__ void compute_hsum_row(
    const float* __restrict__ tb, int row, float* Pw, __half* cbrow, int lane) {
    uint2* cb2 = (uint2*)cbrow;
    if (row < 0 || row >= H) {
        #pragma unroll
        for (int c = 0; c < 4; ++c) cb2[c * 32 + lane] = make_uint2(0u, 0u);
        return;
    }
    const unsigned FULL = 0xffffffffu;
    const float4* __restrict__ rowp = (const float4*)(tb + (size_t)row * W);
    float4* P4 = (float4*)Pw;

    float carry = 0.0f;
    #pragma unroll
    for (int c = 0; c < 4; ++c) {
        float4 q = rowp[c * 32 + lane];
        float p0 = q.x;
        float p1 = p0 + q.y;
        float p2 = p1 + q.z;
        float p3 = p2 + q.w;
        float s = p3;
        #pragma unroll
        for (int off = 1; off < 32; off <<= 1) {
            float n = __shfl_up_sync(FULL, s, off);
            if (lane >= off) s += n;
        }
        const float base = s - p3 + carry;
        P4[c * 32 + lane] = make_float4(base + p0, base + p1, base + p2, base + p3);
        carry += __shfl_sync(FULL, s, 31);
    }
    __syncwarp();
    const float total = carry;
    #pragma unroll
    for (int c = 0; c < 4; ++c) {
        const int g = c * 32 + lane;
        float4 A;
        if (g < 124) {
            float4 Q1 = P4[g + 3];
            float4 Q2 = P4[g + 4];
            A = make_float4(Q1.w, Q2.x, Q2.y, Q2.z);
        } else {
            A = make_float4(total, total, total, total);
        }
        float4 B = (g >= 4) ? P4[g - 4] : make_float4(0.f, 0.f, 0.f, 0.f);
        __half2 ha = __floats2half2_rn(A.x - B.x, A.y - B.y);
        __half2 hb = __floats2half2_rn(A.z - B.z, A.w - B.w);
        uint2 u;
        u.x = *reinterpret_cast<unsigned*>(&ha);
        u.y = *reinterpret_cast<unsigned*>(&hb);
        cb2[g] = u;
    }
}

__device__ __forceinline__ void lane_math(float xv, float tv, float vsum,
                                          float& bce, float& ws, float& it, float& un) {
    const float w   = fmaf(5.0f, fabsf(vsum * KK_INV - tv), 1.0f);
    const float E   = __expf(-fabsf(xv));
    const float u   = 1.0f + E;
    const float sp  = fmaxf(xv, 0.0f) + __logf(u);
    const float inv = __fdividef(1.0f, u);
    const float p   = (xv >= 0.0f) ? inv : E * inv;
    bce += sp - xv * tv;
    ws  += w;
    it  += p * tv * w;
    un  += (p + tv) * w;
}

// ---------------------------------------------------------------------------
// Fused kernel: grid (H/32, BATCH), block 128.
// 4 warps feed a 36-row fp16 circular buffer of hsum rows; all 128 threads run
// the vertical sliding-window + loss math (thread owns 4 columns).
// ---------------------------------------------------------------------------
__global__ __launch_bounds__(128) void fused_kernel(const float* __restrict__ pred,
                                                    const float* __restrict__ targ) {
    __shared__ __half CB[NSLOT][W];      // 36 KB
    __shared__ float  Pscr[4][W];        // 8 KB (per-warp prefix scratch)
    __shared__ float  red[4][128];

    const int b    = blockIdx.y;
    const int tid  = threadIdx.x;
    const int w    = tid >> 5;
    const int lane = tid & 31;
    const int r0   = blockIdx.x * ROWS_PB;

    const float* __restrict__ tb = targ + (size_t)b * HW;
    const float* __restrict__ pb = pred + (size_t)b * HW;
    const float4* __restrict__ tb4 = (const float4*)tb;
    const float4* __restrict__ pb4 = (const float4*)pb;

    // Prologue: hsum rows r0-15 .. r0+15 (31 rows, warp-strided)
    #pragma unroll
    for (int k = 0; k < 8; ++k) {
        const int i = k * 4 + w;
        if (i < 31) {
            const int row = r0 - 15 + i;
            compute_hsum_row(tb, row, Pscr[w], CB[slotof(row)], lane);
        }
    }
    __syncthreads();

    // Initial vertical window
    float4 vs = make_float4(0.f, 0.f, 0.f, 0.f);
    #pragma unroll
    for (int i = 0; i < 31; ++i) {
        const int row = r0 - 15 + i;
        uint2 u = ((uint2*)CB[slotof(row)])[tid];
        float2 a = __half22float2(*reinterpret_cast<__half2*>(&u.x));
        float2 c = __half22float2(*reinterpret_cast<__half2*>(&u.y));
        vs.x += a.x; vs.y += a.y; vs.z += c.x; vs.w += c.y;
    }

    float bce_a = 0.f, wsum_a = 0.f, inter_a = 0.f, uni_a = 0.f;

    for (int gr = 0; gr < ROWS_PB / 4; ++gr) {
        const int r = r0 + gr * 4;
        // Produce the next 4 hsum rows (r+16 .. r+19), one per warp
        {
            const int row = r + 16 + w;
            compute_hsum_row(tb, row, Pscr[w], CB[slotof(row)], lane);
        }
        __syncthreads();

        #pragma unroll
        for (int j = 0; j < 4; ++j) {
            const int rr = r + j;
            const float4 tv = tb4[rr * (W/4) + tid];
            const float4 xv = pb4[rr * (W/4) + tid];

            lane_math(xv.x, tv.x, vs.x, bce_a, wsum_a, inter_a, uni_a);
            lane_math(xv.y, tv.y, vs.y, bce_a, wsum_a, inter_a, uni_a);
            lane_math(xv.z, tv.z, vs.z, bce_a, wsum_a, inter_a, uni_a);
            lane_math(xv.w, tv.w, vs.w, bce_a, wsum_a, inter_a, uni_a);

            // slide: add row rr+16, subtract row rr-15
            uint2 ua = ((uint2*)CB[slotof(rr + 16)])[tid];
            uint2 us = ((uint2*)CB[slotof(rr - 15)])[tid];
            float2 aa = __half22float2(*reinterpret_cast<__half2*>(&ua.x));
            float2 ab = __half22float2(*reinterpret_cast<__half2*>(&ua.y));
            float2 sa = __half22float2(*reinterpret_cast<__half2*>(&us.x));
            float2 sb = __half22float2(*reinterpret_cast<__half2*>(&us.y));
            vs.x += aa.x - sa.x;
            vs.y += aa.y - sa.y;
            vs.z += ab.x - sb.x;
            vs.w += ab.y - sb.y;
        }
        __syncthreads();   // protect ring slots before next group's writes
    }

    // Deterministic block reduction (fixed order)
    red[0][tid] = bce_a;
    red[1][tid] = wsum_a;
    red[2][tid] = inter_a;
    red[3][tid] = uni_a;
    __syncthreads();
    #pragma unroll
    for (int off = 64; off > 0; off >>= 1) {
        if (tid < off) {
            red[0][tid] += red[0][tid + off];
            red[1][tid] += red[1][tid + off];
            red[2][tid] += red[2][tid + off];
            red[3][tid] += red[3][tid + off];
        }
        __syncthreads();
    }
    if (tid == 0) {
        const int blin = b * gridDim.x + blockIdx.x;   // image-major
        g_part[blin][0] = red[0][0];
        g_part[blin][1] = red[1][0];
        g_part[blin][2] = red[2][0];
        g_part[blin][3] = red[3][0];
    }
}

// ---------------------------------------------------------------------------
// Finalize: one block, 256 threads, fixed-order sums.
// ---------------------------------------------------------------------------
__global__ void finalize_kernel(float* __restrict__ out) {
    const int tid = threadIdx.x;
    __shared__ float sb[256];
    __shared__ float res[BATCH];

    float acc = 0.0f;
    #pragma unroll
    for (int j = 0; j < NBLK / 256; ++j) acc += g_part[tid * (NBLK / 256) + j][0];
    sb[tid] = acc;
    __syncthreads();
    #pragma unroll
    for (int off = 128; off > 0; off >>= 1) {
        if (tid < off) sb[tid] += sb[tid + off];
        __syncthreads();
    }
    const float bce = sb[0] * (1.0f / (float)NTOT);

    if (tid < BATCH) {
        float ws = 0.0f, it = 0.0f, un = 0.0f;
        #pragma unroll
        for (int j = 0; j < CHUNKS_PER_IMG; ++j) {
            const int bl = tid * CHUNKS_PER_IMG + j;
            ws += g_part[bl][1];
            it += g_part[bl][2];
            un += g_part[bl][3];
        }
        const float w_bce = (ws * bce + 1e-8f) / (ws + 1e-8f);
        const float w_iou = 1.0f - (it + 1.0f + 1e-8f) / (un - it + 1.0f + 1e-8f);
        res[tid] = w_bce + w_iou;
    }
    __syncthreads();
    if (tid == 0) {
        float a = 0.0f;
        #pragma unroll
        for (int i = 0; i < BATCH; ++i) a += res[i];
        out[0] = a * (1.0f / (float)BATCH);
    }
}

// ---------------------------------------------------------------------------
extern "C" void kernel_launch(void* const* d_in, const int* in_sizes, int n_in,
                              void* d_out, int out_size) {
    const float* y_pred   = (const float*)d_in[0];
    const float* y_target = (const float*)d_in[1];
    float* out = (float*)d_out;

    dim3 g(H / ROWS_PB, BATCH);       // (16, 32) = 512 blocks
    fused_kernel<<<g, 128>>>(y_pred, y_target);
    finalize_kernel<<<1, 256>>>(out);
}